// round 13
// baseline (speedup 1.0000x reference)
#include <cuda_runtime.h>
#include <cuda_bf16.h>
#include <math.h>
#include <stdint.h>

#define BATCH 2
#define LQ 13294
#define LEN_IN 13294
#define DM 256
#define NH 8
#define HD 32
#define MROWS (BATCH * LQ)   // 26588
#define MPAD  26624          // 208 * 128
#define QPR   64             // packed uint4 quads per row (16 chunks * 4 tg)
#define GRID_GEMM 304        // 2 CTAs/SM * 152 SMs (GB300)

// ---------------- scratch (device globals; no allocations allowed) ----------
__device__ float g_value[(size_t)BATCH * LEN_IN * DM];   // [B, LEN_IN, NH, HD]
__device__ float g_offs[(size_t)BATCH * LQ * DM];        // [B, LQ, NH, 16, 2]
__device__ float g_logits[(size_t)BATCH * LQ * NH * 16]; // [B, LQ, NH, 16]

__device__ uint4 g_Apack[(size_t)MPAD * QPR];            // inputf pack, reused for acc
__device__ uint4 g_Qpack[(size_t)MPAD * QPR];            // query pack
__device__ uint4 g_Wvp[256 * QPR];
__device__ uint4 g_Woffp[256 * QPR];
__device__ uint4 g_Wap[128 * QPR];
__device__ uint4 g_Woutp[256 * QPR];

// ---------------- helpers ---------------------------------------------------
__device__ __forceinline__ void mma_bf16(float* d,
    unsigned a0, unsigned a1, unsigned a2, unsigned a3,
    unsigned b0, unsigned b1)
{
    asm volatile(
        "mma.sync.aligned.m16n8k16.row.col.f32.bf16.bf16.f32 "
        "{%0,%1,%2,%3}, {%4,%5,%6,%7}, {%8,%9}, {%0,%1,%2,%3};"
        : "+f"(d[0]), "+f"(d[1]), "+f"(d[2]), "+f"(d[3])
        : "r"(a0), "r"(a1), "r"(a2), "r"(a3), "r"(b0), "r"(b1));
}

__device__ __forceinline__ void cpa16(uint32_t dst, const void* src) {
    asm volatile("cp.async.ca.shared.global [%0], [%1], 16;" :: "r"(dst), "l"(src));
}
#define CPA_COMMIT() asm volatile("cp.async.commit_group;")

__device__ __forceinline__ unsigned pack_hi2(float x0, float x1,
                                             float& l0, float& l1) {
    const __nv_bfloat16 h0 = __float2bfloat16_rn(x0);
    const __nv_bfloat16 h1 = __float2bfloat16_rn(x1);
    l0 = x0 - __bfloat162float(h0);
    l1 = x1 - __bfloat162float(h1);
    __nv_bfloat162 p; p.x = h0; p.y = h1;
    return *reinterpret_cast<unsigned*>(&p);
}
__device__ __forceinline__ unsigned pack_lo2(float l0, float l1) {
    __nv_bfloat162 p;
    p.x = __float2bfloat16_rn(l0);
    p.y = __float2bfloat16_rn(l1);
    return *reinterpret_cast<unsigned*>(&p);
}
__device__ __forceinline__ uint4 pack_quad(float x0, float x1, float x2, float x3) {
    float l0, l1, l2, l3;
    uint4 q;
    q.x = pack_hi2(x0, x1, l0, l1);
    q.y = pack_hi2(x2, x3, l2, l3);
    q.z = pack_lo2(l0, l1);
    q.w = pack_lo2(l2, l3);
    return q;
}

// ---------------- fused prepack (A0, A1, all weights in one launch) ----------
#define APART (2u * MPAD * 64u)
__global__ __launch_bounds__(256) void prepack_all(
    const float* __restrict__ A0, const float* __restrict__ A1,
    uint4* __restrict__ P0, uint4* __restrict__ P1,
    const float* __restrict__ Wv,  const float* __restrict__ Woff,
    const float* __restrict__ Wa,  const float* __restrict__ Wout,
    uint4* __restrict__ wvp, uint4* __restrict__ woffp,
    uint4* __restrict__ wap, uint4* __restrict__ woutp)
{
    const unsigned t = blockIdx.x * 256 + threadIdx.x;
    if (t < APART) {
        const unsigned HALF = (unsigned)MPAD * 64;
        const float* A = (t < HALF) ? A0 : A1;
        uint4* P = (t < HALF) ? P0 : P1;
        const unsigned lt = (t < HALF) ? t : t - HALF;
        const unsigned row = lt >> 6;
        const unsigned c = (lt >> 2) & 15, tg = lt & 3;
        float x0 = 0.f, x1 = 0.f, x2 = 0.f, x3 = 0.f;
        if (row < (unsigned)MROWS) {
            const float* a = A + (size_t)row * 256 + c * 16 + 2 * tg;
            x0 = a[0]; x1 = a[1]; x2 = a[8]; x3 = a[9];
        }
        P[lt] = pack_quad(x0, x1, x2, x3);
    } else {
        const unsigned u = t - APART;   // < 57344
        const float* B; uint4* Bp; unsigned N, lt;
        if (u < 16384)      { B = Wv;   Bp = wvp;   N = 256; lt = u; }
        else if (u < 32768) { B = Woff; Bp = woffp; N = 256; lt = u - 16384; }
        else if (u < 40960) { B = Wa;   Bp = wap;   N = 128; lt = u - 32768; }
        else                { B = Wout; Bp = woutp; N = 256; lt = u - 40960; }
        const unsigned col = lt >> 6;
        const unsigned c = (lt >> 2) & 15, tg = lt & 3;
        const unsigned k = c * 16 + 2 * tg;
        const float x0 = B[(k + 0) * N + col];
        const float x1 = B[(k + 1) * N + col];
        const float x2 = B[(k + 8) * N + col];
        const float x3 = B[(k + 9) * N + col];
        Bp[lt] = pack_quad(x0, x1, x2, x3);
    }
}

// ---------------- tensor-core GEMM tile (3xBF16 split, prepacked) -----------
// BM=BN=128, BK=32, 256 threads (8 warps: 2 M x 4 N), warp tile 64x32.
#define RQ 12
#define TILE_QUADS (128 * RQ)                 // 1536 quads = 24 KB
#define GSMEM_BYTES (4 * TILE_QUADS * 16)     // 96 KB

struct GemmJob {
    const uint4* Ap;
    const uint4* Bp;
    const float* bias;
    float* C;
    int N;       // 256 or 128
    int ncols;   // N / 128
    int ntiles;  // ncols * 208
};

__device__ __forceinline__ void gemm_tile(
    const uint4* __restrict__ Ap, const uint4* __restrict__ Bp,
    const float* __restrict__ bias, float* __restrict__ C,
    int N, int bm, int bn, uint4* smem)
{
    const int tid = threadIdx.x;
    const int lane = tid & 31;
    const int wid = tid >> 5;
    const int warp_m = wid & 1;
    const int warp_n = wid >> 1;
    const int g  = lane >> 2;
    const int tg = lane & 3;

    const int lrow0 = tid >> 3;
    const int lf    = tid & 7;

    const uint32_t smem_u32 = (uint32_t)__cvta_generic_to_shared(smem);
    const int NCH = 8;

    float acc[4][4][4];
    #pragma unroll
    for (int i = 0; i < 4; ++i)
        #pragma unroll
        for (int j = 0; j < 4; ++j)
            #pragma unroll
            for (int e = 0; e < 4; ++e) acc[i][j][e] = 0.f;

    auto load_tile = [&](int buf, int c) {
        const uint32_t abase = smem_u32 + (uint32_t)(buf * 2 * TILE_QUADS) * 16;
        const uint32_t bbase = abase + (uint32_t)TILE_QUADS * 16;
        #pragma unroll
        for (int p = 0; p < 4; ++p) {
            const int row = lrow0 + p * 32;
            cpa16(abase + (uint32_t)(row * RQ + lf) * 16,
                  Ap + (size_t)(bm + row) * QPR + c * 8 + lf);
        }
        #pragma unroll
        for (int p = 0; p < 4; ++p) {
            const int col = lrow0 + p * 32;
            cpa16(bbase + (uint32_t)(col * RQ + lf) * 16,
                  Bp + (size_t)(bn + col) * QPR + c * 8 + lf);
        }
    };

    load_tile(0, 0);
    CPA_COMMIT();

    for (int c = 0; c < NCH; ++c) {
        const int cur = c & 1;
        if (c + 1 < NCH) {
            load_tile(cur ^ 1, c + 1);
            CPA_COMMIT();
            asm volatile("cp.async.wait_group 1;");
        } else {
            asm volatile("cp.async.wait_group 0;");
        }
        __syncthreads();

        const uint4* As_ = smem + cur * 2 * TILE_QUADS;
        const uint4* Bs_ = As_ + TILE_QUADS;

        #pragma unroll
        for (int cl = 0; cl < 2; ++cl) {
            const int qoff = cl * 4 + tg;
            uint4 bf[4];
            #pragma unroll
            for (int ni = 0; ni < 4; ++ni)
                bf[ni] = Bs_[(warp_n * 32 + ni * 8 + g) * RQ + qoff];

            #pragma unroll
            for (int mi = 0; mi < 4; ++mi) {
                const uint4 a0 = As_[(warp_m * 64 + mi * 16 + g) * RQ + qoff];
                const uint4 a1 = As_[(warp_m * 64 + mi * 16 + g + 8) * RQ + qoff];
                #pragma unroll
                for (int ni = 0; ni < 4; ++ni) {
                    mma_bf16(acc[mi][ni], a0.x, a1.x, a0.y, a1.y, bf[ni].x, bf[ni].y);
                    mma_bf16(acc[mi][ni], a0.x, a1.x, a0.y, a1.y, bf[ni].z, bf[ni].w);
                    mma_bf16(acc[mi][ni], a0.z, a1.z, a0.w, a1.w, bf[ni].x, bf[ni].y);
                }
            }
        }
        __syncthreads();   // protects smem reuse across chunks/tiles
    }

    #pragma unroll
    for (int mi = 0; mi < 4; ++mi) {
        const int row0 = bm + warp_m * 64 + mi * 16 + g;
        const int row1 = row0 + 8;
        #pragma unroll
        for (int ni = 0; ni < 4; ++ni) {
            const int col = bn + warp_n * 32 + ni * 8 + 2 * tg;
            const float bx = bias[col], by = bias[col + 1];
            if (row0 < MROWS) {
                float2 v = {acc[mi][ni][0] + bx, acc[mi][ni][1] + by};
                *reinterpret_cast<float2*>(C + (size_t)row0 * N + col) = v;
            }
            if (row1 < MROWS) {
                float2 v = {acc[mi][ni][2] + bx, acc[mi][ni][3] + by};
                *reinterpret_cast<float2*>(C + (size_t)row1 * N + col) = v;
            }
        }
    }
}

__global__ __launch_bounds__(256, 2) void fused_gemm_kernel(
    GemmJob j0, GemmJob j1, GemmJob j2, int njobs, int total)
{
    extern __shared__ uint4 smem[];
    for (int t = blockIdx.x; t < total; t += gridDim.x) {
        GemmJob jb = j0;
        int lt = t;
        if (njobs > 1 && lt >= jb.ntiles) {
            lt -= jb.ntiles; jb = j1;
            if (njobs > 2 && lt >= jb.ntiles) { lt -= jb.ntiles; jb = j2; }
        }
        int bm, bn;
        if (jb.ncols == 2) { bm = (lt >> 1) * 128; bn = (lt & 1) * 128; }
        else               { bm = lt * 128;        bn = 0; }
        gemm_tile(jb.Ap, jb.Bp, jb.bias, jb.C, jb.N, bm, bn, smem);
    }
}

// ---------------- sampling + softmax + fused bf16 hi/lo packing -------------
// One block per (b,q); one warp per head, warps independent.
// Gather explicitly software-pipelined: 8 independent LDG.128s issued into
// registers BEFORE any consuming FFMA (MLP=8 vs compiler's ~4), two batches.
// Levels 0-1 __ldcg (L2-only), levels 2-3 __ldg (L1-resident).
__global__ __launch_bounds__(256, 3) void sample_kernel(
    const float* __restrict__ refp, uint4* __restrict__ AccPack)
{
    __shared__ __align__(16) int2  comb[NH][16][4];  // {byte offset, weight bits}
    __shared__ __align__(16) float swacc[NH][32];    // per-warp channel patch

    const int bq = blockIdx.x;
    const int b  = (bq >= LQ) ? 1 : 0;
    const int tid = threadIdx.x;
    const int h  = tid >> 5;
    const int lane = tid & 31;

    // ---- softmax over the 16 logits ----
    float logit = -INFINITY;
    if (lane < 16) logit = g_logits[((unsigned)bq * NH + h) * 16 + lane];
    float m = logit;
    #pragma unroll
    for (int o = 16; o > 0; o >>= 1) m = fmaxf(m, __shfl_xor_sync(0xffffffffu, m, o));
    float e = (lane < 16) ? __expf(logit - m) : 0.f;
    float s = e;
    #pragma unroll
    for (int o = 16; o > 0; o >>= 1) s += __shfl_xor_sync(0xffffffffu, s, o);
    const float wt = e / s;

    if (lane < 16) {
        const int LH[4] = {100, 50, 25, 13};
        const int LS[4] = {0, 10000, 12500, 13125};
        const int l = lane >> 2;
        const int w = LH[l], hh = LH[l], s0 = LS[l];
        const float lw = (float)w, lh = (float)hh;

        const float2 off = *reinterpret_cast<const float2*>(
            g_offs + (((unsigned)bq * NH + h) * 16 + lane) * 2);
        const float2 rp = *reinterpret_cast<const float2*>(refp + (unsigned)bq * 8 + l * 2);

        const float x = (rp.x + off.x / lw) * lw - 0.5f;
        const float y = (rp.y + off.y / lh) * lh - 0.5f;
        const float fx = floorf(x), fy = floorf(y);
        const float tx = x - fx, ty = y - fy;
        const int jx = (int)fx, jy = (int)fy;

        const bool xv0 = (jx >= 0) && (jx < w);
        const bool xv1 = (jx + 1 >= 0) && (jx + 1 < w);
        const bool yv0 = (jy >= 0) && (jy < hh);
        const bool yv1 = (jy + 1 >= 0) && (jy + 1 < hh);

        const int cx0 = min(max(jx, 0), w - 1);
        const int cx1 = min(max(jx + 1, 0), w - 1);
        const int cy0 = min(max(jy, 0), hh - 1);
        const int cy1 = min(max(jy + 1, 0), hh - 1);

        const float wx1 = tx, wx0 = 1.f - tx;
        const float wy1 = ty, wy0 = 1.f - ty;

        const float w0 = (xv0 && yv0) ? wt * wx0 * wy0 : 0.f;
        const float w1 = (xv1 && yv0) ? wt * wx1 * wy0 : 0.f;
        const float w2 = (xv0 && yv1) ? wt * wx0 * wy1 : 0.f;
        const float w3 = (xv1 && yv1) ? wt * wx1 * wy1 : 0.f;

        comb[h][lane][0] = make_int2((s0 + cy0 * w + cx0) << 10, __float_as_int(w0));
        comb[h][lane][1] = make_int2((s0 + cy0 * w + cx1) << 10, __float_as_int(w1));
        comb[h][lane][2] = make_int2((s0 + cy1 * w + cx0) << 10, __float_as_int(w2));
        comb[h][lane][3] = make_int2((s0 + cy1 * w + cx1) << 10, __float_as_int(w3));
    }
    __syncwarp();

    // ---- gather, software-pipelined in two MLP=8 batches ----
    const int sub = lane >> 3;
    const int cl  = lane & 7;
    const char* __restrict__ base = (const char*)(
        g_value + ((unsigned)b * LEN_IN) * DM + h * HD + cl * 4);

    float4 acc = {0.f, 0.f, 0.f, 0.f};

    // batch 1: points 0-7 (levels 0-1), L2-only
    {
        int2 cw[8];
        #pragma unroll
        for (int p = 0; p < 8; ++p) cw[p] = comb[h][p][sub];
        float4 v[8];
        #pragma unroll
        for (int p = 0; p < 8; ++p)
            v[p] = __ldcg(reinterpret_cast<const float4*>(base + cw[p].x));
        #pragma unroll
        for (int p = 0; p < 8; ++p) {
            const float w = __int_as_float(cw[p].y);
            acc.x += w * v[p].x;
            acc.y += w * v[p].y;
            acc.z += w * v[p].z;
            acc.w += w * v[p].w;
        }
    }
    // batch 2: points 8-15 (levels 2-3), L1-resident
    {
        int2 cw[8];
        #pragma unroll
        for (int p = 0; p < 8; ++p) cw[p] = comb[h][p + 8][sub];
        float4 v[8];
        #pragma unroll
        for (int p = 0; p < 8; ++p)
            v[p] = __ldg(reinterpret_cast<const float4*>(base + cw[p].x));
        #pragma unroll
        for (int p = 0; p < 8; ++p) {
            const float w = __int_as_float(cw[p].y);
            acc.x += w * v[p].x;
            acc.y += w * v[p].y;
            acc.z += w * v[p].z;
            acc.w += w * v[p].w;
        }
    }

    // reduce over the 4 corners (lanes cl, cl+8, cl+16, cl+24)
    #pragma unroll
    for (int o = 8; o <= 16; o <<= 1) {
        acc.x += __shfl_xor_sync(0xffffffffu, acc.x, o);
        acc.y += __shfl_xor_sync(0xffffffffu, acc.y, o);
        acc.z += __shfl_xor_sync(0xffffffffu, acc.z, o);
        acc.w += __shfl_xor_sync(0xffffffffu, acc.w, o);
    }
    if (sub == 0)
        *reinterpret_cast<float4*>(&swacc[h][cl * 4]) = acc;
    __syncwarp();

    // ---- pack this head's 32 channels into 8 bf16 hi/lo quads ----
    if (lane < 8) {
        const int cloc = lane >> 2, tg = lane & 3;
        const int bs = cloc * 16 + 2 * tg;
        AccPack[(size_t)bq * QPR + h * 8 + cloc * 4 + tg] =
            pack_quad(swacc[h][bs], swacc[h][bs + 1],
                      swacc[h][bs + 8], swacc[h][bs + 9]);
    }
}

// ---------------- launch ----------------------------------------------------
extern "C" void kernel_launch(void* const* d_in, const int* in_sizes, int n_in,
                              void* d_out, int out_size)
{
    const float* query  = (const float*)d_in[0];
    const float* refp   = (const float*)d_in[1];
    const float* inputf = (const float*)d_in[2];
    const float* Wv   = (const float*)d_in[4];
    const float* bv   = (const float*)d_in[5];
    const float* Woff = (const float*)d_in[6];
    const float* boff = (const float*)d_in[7];
    const float* Wa   = (const float*)d_in[8];
    const float* ba   = (const float*)d_in[9];
    const float* Wout = (const float*)d_in[10];
    const float* bout = (const float*)d_in[11];
    float* out = (float*)d_out;

    float *valuep, *offsp, *logitsp;
    uint4 *apackp, *qpackp, *wvp, *woffp, *wap, *woutp;
    cudaGetSymbolAddress((void**)&valuep,  g_value);
    cudaGetSymbolAddress((void**)&offsp,   g_offs);
    cudaGetSymbolAddress((void**)&logitsp, g_logits);
    cudaGetSymbolAddress((void**)&apackp,  g_Apack);
    cudaGetSymbolAddress((void**)&qpackp,  g_Qpack);
    cudaGetSymbolAddress((void**)&wvp,     g_Wvp);
    cudaGetSymbolAddress((void**)&woffp,   g_Woffp);
    cudaGetSymbolAddress((void**)&wap,     g_Wap);
    cudaGetSymbolAddress((void**)&woutp,   g_Woutp);

    static bool attr_set = false;
    if (!attr_set) {
        cudaFuncSetAttribute(fused_gemm_kernel,
                             cudaFuncAttributeMaxDynamicSharedMemorySize, GSMEM_BYTES);
        attr_set = true;
    }

    // fused prepack: A0, A1, all weights
    const unsigned npre = APART + 57344u;
    prepack_all<<<(npre + 255) / 256, 256>>>(
        inputf, query, apackp, qpackp,
        Wv, Woff, Wa, Wout, wvp, woffp, wap, woutp);

    // fused GEMMs 1-3: value / offs / logits  (416 + 416 + 208 = 1040 tiles)
    GemmJob jv  = {apackp, wvp,   bv,   valuep,  256, 2, 416};
    GemmJob jo  = {qpackp, woffp, boff, offsp,   256, 2, 416};
    GemmJob jl  = {qpackp, wap,   ba,   logitsp, 128, 1, 208};
    fused_gemm_kernel<<<GRID_GEMM, 256, GSMEM_BYTES>>>(jv, jo, jl, 3, 1040);

    // softmax + bilinear sampling -> packed acc (writes directly into Apack)
    sample_kernel<<<BATCH * LQ, 256>>>(refp, apackp);

    // out = acc @ W_out + b_out
    GemmJob jout = {apackp, woutp, bout, out, 256, 2, 416};
    fused_gemm_kernel<<<GRID_GEMM, 256, GSMEM_BYTES>>>(jout, jout, jout, 1, 416);
}

// round 14
// speedup vs baseline: 1.2641x; 1.2641x over previous
#include <cuda_runtime.h>
#include <cuda_bf16.h>
#include <math.h>
#include <stdint.h>

#define BATCH 2
#define LQ 13294
#define LEN_IN 13294
#define DM 256
#define NH 8
#define HD 32
#define MROWS (BATCH * LQ)   // 26588
#define MPAD  26624          // 208 * 128
#define QPR   64             // packed uint4 quads per row (16 chunks * 4 tg)
#define GRID_GEMM 304        // 2 CTAs/SM * 152 SMs (GB300)

// ---------------- scratch (device globals; no allocations allowed) ----------
__device__ float g_value[(size_t)BATCH * LEN_IN * DM];   // [B, LEN_IN, NH, HD]
__device__ float g_offs[(size_t)BATCH * LQ * DM];        // [B, LQ, NH, 16, 2]
__device__ float g_logits[(size_t)BATCH * LQ * NH * 16]; // [B, LQ, NH, 16]

__device__ uint4 g_Apack[(size_t)MPAD * QPR];            // inputf pack, reused for acc
__device__ uint4 g_Qpack[(size_t)MPAD * QPR];            // query pack
__device__ uint4 g_Wvp[256 * QPR];
__device__ uint4 g_Woffp[256 * QPR];
__device__ uint4 g_Wap[128 * QPR];
__device__ uint4 g_Woutp[256 * QPR];

// ---------------- helpers ---------------------------------------------------
__device__ __forceinline__ void mma_bf16(float* d,
    unsigned a0, unsigned a1, unsigned a2, unsigned a3,
    unsigned b0, unsigned b1)
{
    asm volatile(
        "mma.sync.aligned.m16n8k16.row.col.f32.bf16.bf16.f32 "
        "{%0,%1,%2,%3}, {%4,%5,%6,%7}, {%8,%9}, {%0,%1,%2,%3};"
        : "+f"(d[0]), "+f"(d[1]), "+f"(d[2]), "+f"(d[3])
        : "r"(a0), "r"(a1), "r"(a2), "r"(a3), "r"(b0), "r"(b1));
}

__device__ __forceinline__ void cpa16(uint32_t dst, const void* src) {
    asm volatile("cp.async.ca.shared.global [%0], [%1], 16;" :: "r"(dst), "l"(src));
}
#define CPA_COMMIT() asm volatile("cp.async.commit_group;")

__device__ __forceinline__ unsigned pack_hi2(float x0, float x1,
                                             float& l0, float& l1) {
    const __nv_bfloat16 h0 = __float2bfloat16_rn(x0);
    const __nv_bfloat16 h1 = __float2bfloat16_rn(x1);
    l0 = x0 - __bfloat162float(h0);
    l1 = x1 - __bfloat162float(h1);
    __nv_bfloat162 p; p.x = h0; p.y = h1;
    return *reinterpret_cast<unsigned*>(&p);
}
__device__ __forceinline__ unsigned pack_lo2(float l0, float l1) {
    __nv_bfloat162 p;
    p.x = __float2bfloat16_rn(l0);
    p.y = __float2bfloat16_rn(l1);
    return *reinterpret_cast<unsigned*>(&p);
}
__device__ __forceinline__ uint4 pack_quad(float x0, float x1, float x2, float x3) {
    float l0, l1, l2, l3;
    uint4 q;
    q.x = pack_hi2(x0, x1, l0, l1);
    q.y = pack_hi2(x2, x3, l2, l3);
    q.z = pack_lo2(l0, l1);
    q.w = pack_lo2(l2, l3);
    return q;
}

// ---------------- fused prepack (A0, A1, all weights in one launch) ----------
#define APART (2u * MPAD * 64u)
__global__ __launch_bounds__(256) void prepack_all(
    const float* __restrict__ A0, const float* __restrict__ A1,
    uint4* __restrict__ P0, uint4* __restrict__ P1,
    const float* __restrict__ Wv,  const float* __restrict__ Woff,
    const float* __restrict__ Wa,  const float* __restrict__ Wout,
    uint4* __restrict__ wvp, uint4* __restrict__ woffp,
    uint4* __restrict__ wap, uint4* __restrict__ woutp)
{
    const unsigned t = blockIdx.x * 256 + threadIdx.x;
    if (t < APART) {
        const unsigned HALF = (unsigned)MPAD * 64;
        const float* A = (t < HALF) ? A0 : A1;
        uint4* P = (t < HALF) ? P0 : P1;
        const unsigned lt = (t < HALF) ? t : t - HALF;
        const unsigned row = lt >> 6;
        const unsigned c = (lt >> 2) & 15, tg = lt & 3;
        float x0 = 0.f, x1 = 0.f, x2 = 0.f, x3 = 0.f;
        if (row < (unsigned)MROWS) {
            const float* a = A + (size_t)row * 256 + c * 16 + 2 * tg;
            x0 = a[0]; x1 = a[1]; x2 = a[8]; x3 = a[9];
        }
        P[lt] = pack_quad(x0, x1, x2, x3);
    } else {
        const unsigned u = t - APART;   // < 57344
        const float* B; uint4* Bp; unsigned N, lt;
        if (u < 16384)      { B = Wv;   Bp = wvp;   N = 256; lt = u; }
        else if (u < 32768) { B = Woff; Bp = woffp; N = 256; lt = u - 16384; }
        else if (u < 40960) { B = Wa;   Bp = wap;   N = 128; lt = u - 32768; }
        else                { B = Wout; Bp = woutp; N = 256; lt = u - 40960; }
        const unsigned col = lt >> 6;
        const unsigned c = (lt >> 2) & 15, tg = lt & 3;
        const unsigned k = c * 16 + 2 * tg;
        const float x0 = B[(k + 0) * N + col];
        const float x1 = B[(k + 1) * N + col];
        const float x2 = B[(k + 8) * N + col];
        const float x3 = B[(k + 9) * N + col];
        Bp[lt] = pack_quad(x0, x1, x2, x3);
    }
}

// ---------------- tensor-core GEMM tile (3xBF16 split, prepacked) -----------
// BM=BN=128, BK=32, 256 threads (8 warps: 2 M x 4 N), warp tile 64x32.
#define RQ 12
#define TILE_QUADS (128 * RQ)                 // 1536 quads = 24 KB
#define GSMEM_BYTES (4 * TILE_QUADS * 16)     // 96 KB

struct GemmJob {
    const uint4* Ap;
    const uint4* Bp;
    const float* bias;
    float* C;
    int N;       // 256 or 128
    int ncols;   // N / 128
    int ntiles;  // ncols * 208
};

__device__ __forceinline__ void gemm_tile(
    const uint4* __restrict__ Ap, const uint4* __restrict__ Bp,
    const float* __restrict__ bias, float* __restrict__ C,
    int N, int bm, int bn, uint4* smem)
{
    const int tid = threadIdx.x;
    const int lane = tid & 31;
    const int wid = tid >> 5;
    const int warp_m = wid & 1;
    const int warp_n = wid >> 1;
    const int g  = lane >> 2;
    const int tg = lane & 3;

    const int lrow0 = tid >> 3;
    const int lf    = tid & 7;

    const uint32_t smem_u32 = (uint32_t)__cvta_generic_to_shared(smem);
    const int NCH = 8;

    float acc[4][4][4];
    #pragma unroll
    for (int i = 0; i < 4; ++i)
        #pragma unroll
        for (int j = 0; j < 4; ++j)
            #pragma unroll
            for (int e = 0; e < 4; ++e) acc[i][j][e] = 0.f;

    auto load_tile = [&](int buf, int c) {
        const uint32_t abase = smem_u32 + (uint32_t)(buf * 2 * TILE_QUADS) * 16;
        const uint32_t bbase = abase + (uint32_t)TILE_QUADS * 16;
        #pragma unroll
        for (int p = 0; p < 4; ++p) {
            const int row = lrow0 + p * 32;
            cpa16(abase + (uint32_t)(row * RQ + lf) * 16,
                  Ap + (size_t)(bm + row) * QPR + c * 8 + lf);
        }
        #pragma unroll
        for (int p = 0; p < 4; ++p) {
            const int col = lrow0 + p * 32;
            cpa16(bbase + (uint32_t)(col * RQ + lf) * 16,
                  Bp + (size_t)(bn + col) * QPR + c * 8 + lf);
        }
    };

    load_tile(0, 0);
    CPA_COMMIT();

    for (int c = 0; c < NCH; ++c) {
        const int cur = c & 1;
        if (c + 1 < NCH) {
            load_tile(cur ^ 1, c + 1);
            CPA_COMMIT();
            asm volatile("cp.async.wait_group 1;");
        } else {
            asm volatile("cp.async.wait_group 0;");
        }
        __syncthreads();

        const uint4* As_ = smem + cur * 2 * TILE_QUADS;
        const uint4* Bs_ = As_ + TILE_QUADS;

        #pragma unroll
        for (int cl = 0; cl < 2; ++cl) {
            const int qoff = cl * 4 + tg;
            uint4 bf[4];
            #pragma unroll
            for (int ni = 0; ni < 4; ++ni)
                bf[ni] = Bs_[(warp_n * 32 + ni * 8 + g) * RQ + qoff];

            #pragma unroll
            for (int mi = 0; mi < 4; ++mi) {
                const uint4 a0 = As_[(warp_m * 64 + mi * 16 + g) * RQ + qoff];
                const uint4 a1 = As_[(warp_m * 64 + mi * 16 + g + 8) * RQ + qoff];
                #pragma unroll
                for (int ni = 0; ni < 4; ++ni) {
                    mma_bf16(acc[mi][ni], a0.x, a1.x, a0.y, a1.y, bf[ni].x, bf[ni].y);
                    mma_bf16(acc[mi][ni], a0.x, a1.x, a0.y, a1.y, bf[ni].z, bf[ni].w);
                    mma_bf16(acc[mi][ni], a0.z, a1.z, a0.w, a1.w, bf[ni].x, bf[ni].y);
                }
            }
        }
        __syncthreads();   // protects smem reuse across chunks/tiles
    }

    #pragma unroll
    for (int mi = 0; mi < 4; ++mi) {
        const int row0 = bm + warp_m * 64 + mi * 16 + g;
        const int row1 = row0 + 8;
        #pragma unroll
        for (int ni = 0; ni < 4; ++ni) {
            const int col = bn + warp_n * 32 + ni * 8 + 2 * tg;
            const float bx = bias[col], by = bias[col + 1];
            if (row0 < MROWS) {
                float2 v = {acc[mi][ni][0] + bx, acc[mi][ni][1] + by};
                *reinterpret_cast<float2*>(C + (size_t)row0 * N + col) = v;
            }
            if (row1 < MROWS) {
                float2 v = {acc[mi][ni][2] + bx, acc[mi][ni][3] + by};
                *reinterpret_cast<float2*>(C + (size_t)row1 * N + col) = v;
            }
        }
    }
}

__global__ __launch_bounds__(256, 2) void fused_gemm_kernel(
    GemmJob j0, GemmJob j1, GemmJob j2, int njobs, int total)
{
    extern __shared__ uint4 smem[];
    for (int t = blockIdx.x; t < total; t += gridDim.x) {
        GemmJob jb = j0;
        int lt = t;
        if (njobs > 1 && lt >= jb.ntiles) {
            lt -= jb.ntiles; jb = j1;
            if (njobs > 2 && lt >= jb.ntiles) { lt -= jb.ntiles; jb = j2; }
        }
        int bm, bn;
        if (jb.ncols == 2) { bm = (lt >> 1) * 128; bn = (lt & 1) * 128; }
        else               { bm = lt * 128;        bn = 0; }
        gemm_tile(jb.Ap, jb.Bp, jb.bias, jb.C, jb.N, bm, bn, smem);
    }
}

// ---------------- sampling + softmax + fused bf16 hi/lo packing -------------
// One block per (b,q); one warp per head, warps independent.
// Gather batched per level-group: 8 independent LDG.128s issued before any
// consuming FFMA (addresses read from smem at issue; weights re-read from
// smem at consume — keeps live regs ~55, no spill, no min-blocks cap).
__global__ __launch_bounds__(256) void sample_kernel(
    const float* __restrict__ refp, uint4* __restrict__ AccPack)
{
    __shared__ __align__(16) int2  comb[NH][16][4];  // {byte offset, weight bits}
    __shared__ __align__(16) float swacc[NH][32];    // per-warp channel patch

    const int bq = blockIdx.x;
    const int b  = (bq >= LQ) ? 1 : 0;
    const int tid = threadIdx.x;
    const int h  = tid >> 5;
    const int lane = tid & 31;

    // ---- softmax over the 16 logits ----
    float logit = -INFINITY;
    if (lane < 16) logit = g_logits[((unsigned)bq * NH + h) * 16 + lane];
    float m = logit;
    #pragma unroll
    for (int o = 16; o > 0; o >>= 1) m = fmaxf(m, __shfl_xor_sync(0xffffffffu, m, o));
    float e = (lane < 16) ? __expf(logit - m) : 0.f;
    float s = e;
    #pragma unroll
    for (int o = 16; o > 0; o >>= 1) s += __shfl_xor_sync(0xffffffffu, s, o);
    const float wt = e / s;

    if (lane < 16) {
        const int LH[4] = {100, 50, 25, 13};
        const int LS[4] = {0, 10000, 12500, 13125};
        const int l = lane >> 2;
        const int w = LH[l], hh = LH[l], s0 = LS[l];
        const float lw = (float)w, lh = (float)hh;

        const float2 off = *reinterpret_cast<const float2*>(
            g_offs + (((unsigned)bq * NH + h) * 16 + lane) * 2);
        const float2 rp = *reinterpret_cast<const float2*>(refp + (unsigned)bq * 8 + l * 2);

        const float x = (rp.x + off.x / lw) * lw - 0.5f;
        const float y = (rp.y + off.y / lh) * lh - 0.5f;
        const float fx = floorf(x), fy = floorf(y);
        const float tx = x - fx, ty = y - fy;
        const int jx = (int)fx, jy = (int)fy;

        const bool xv0 = (jx >= 0) && (jx < w);
        const bool xv1 = (jx + 1 >= 0) && (jx + 1 < w);
        const bool yv0 = (jy >= 0) && (jy < hh);
        const bool yv1 = (jy + 1 >= 0) && (jy + 1 < hh);

        const int cx0 = min(max(jx, 0), w - 1);
        const int cx1 = min(max(jx + 1, 0), w - 1);
        const int cy0 = min(max(jy, 0), hh - 1);
        const int cy1 = min(max(jy + 1, 0), hh - 1);

        const float wx1 = tx, wx0 = 1.f - tx;
        const float wy1 = ty, wy0 = 1.f - ty;

        const float w0 = (xv0 && yv0) ? wt * wx0 * wy0 : 0.f;
        const float w1 = (xv1 && yv0) ? wt * wx1 * wy0 : 0.f;
        const float w2 = (xv0 && yv1) ? wt * wx0 * wy1 : 0.f;
        const float w3 = (xv1 && yv1) ? wt * wx1 * wy1 : 0.f;

        comb[h][lane][0] = make_int2((s0 + cy0 * w + cx0) << 10, __float_as_int(w0));
        comb[h][lane][1] = make_int2((s0 + cy0 * w + cx1) << 10, __float_as_int(w1));
        comb[h][lane][2] = make_int2((s0 + cy1 * w + cx0) << 10, __float_as_int(w2));
        comb[h][lane][3] = make_int2((s0 + cy1 * w + cx1) << 10, __float_as_int(w3));
    }
    __syncwarp();

    // ---- gather: two batches of 8 independent LDG.128 ----
    const int sub = lane >> 3;
    const int cl  = lane & 7;
    const char* __restrict__ base = (const char*)(
        g_value + ((unsigned)b * LEN_IN) * DM + h * HD + cl * 4);

    float4 acc = {0.f, 0.f, 0.f, 0.f};

    // batch 1: points 0-7 (levels 0-1), L2-only
    {
        float4 v[8];
        #pragma unroll
        for (int p = 0; p < 8; ++p)
            v[p] = __ldcg(reinterpret_cast<const float4*>(base + comb[h][p][sub].x));
        #pragma unroll
        for (int p = 0; p < 8; ++p) {
            const float w = __int_as_float(comb[h][p][sub].y);
            acc.x += w * v[p].x;
            acc.y += w * v[p].y;
            acc.z += w * v[p].z;
            acc.w += w * v[p].w;
        }
    }
    // batch 2: points 8-15 (levels 2-3), L1-resident
    {
        float4 v[8];
        #pragma unroll
        for (int p = 0; p < 8; ++p)
            v[p] = __ldg(reinterpret_cast<const float4*>(base + comb[h][p + 8][sub].x));
        #pragma unroll
        for (int p = 0; p < 8; ++p) {
            const float w = __int_as_float(comb[h][p + 8][sub].y);
            acc.x += w * v[p].x;
            acc.y += w * v[p].y;
            acc.z += w * v[p].z;
            acc.w += w * v[p].w;
        }
    }

    // reduce over the 4 corners (lanes cl, cl+8, cl+16, cl+24)
    #pragma unroll
    for (int o = 8; o <= 16; o <<= 1) {
        acc.x += __shfl_xor_sync(0xffffffffu, acc.x, o);
        acc.y += __shfl_xor_sync(0xffffffffu, acc.y, o);
        acc.z += __shfl_xor_sync(0xffffffffu, acc.z, o);
        acc.w += __shfl_xor_sync(0xffffffffu, acc.w, o);
    }
    if (sub == 0)
        *reinterpret_cast<float4*>(&swacc[h][cl * 4]) = acc;
    __syncwarp();

    // ---- pack this head's 32 channels into 8 bf16 hi/lo quads ----
    if (lane < 8) {
        const int cloc = lane >> 2, tg = lane & 3;
        const int bs = cloc * 16 + 2 * tg;
        AccPack[(size_t)bq * QPR + h * 8 + cloc * 4 + tg] =
            pack_quad(swacc[h][bs], swacc[h][bs + 1],
                      swacc[h][bs + 8], swacc[h][bs + 9]);
    }
}

// ---------------- launch ----------------------------------------------------
extern "C" void kernel_launch(void* const* d_in, const int* in_sizes, int n_in,
                              void* d_out, int out_size)
{
    const float* query  = (const float*)d_in[0];
    const float* refp   = (const float*)d_in[1];
    const float* inputf = (const float*)d_in[2];
    const float* Wv   = (const float*)d_in[4];
    const float* bv   = (const float*)d_in[5];
    const float* Woff = (const float*)d_in[6];
    const float* boff = (const float*)d_in[7];
    const float* Wa   = (const float*)d_in[8];
    const float* ba   = (const float*)d_in[9];
    const float* Wout = (const float*)d_in[10];
    const float* bout = (const float*)d_in[11];
    float* out = (float*)d_out;

    float *valuep, *offsp, *logitsp;
    uint4 *apackp, *qpackp, *wvp, *woffp, *wap, *woutp;
    cudaGetSymbolAddress((void**)&valuep,  g_value);
    cudaGetSymbolAddress((void**)&offsp,   g_offs);
    cudaGetSymbolAddress((void**)&logitsp, g_logits);
    cudaGetSymbolAddress((void**)&apackp,  g_Apack);
    cudaGetSymbolAddress((void**)&qpackp,  g_Qpack);
    cudaGetSymbolAddress((void**)&wvp,     g_Wvp);
    cudaGetSymbolAddress((void**)&woffp,   g_Woffp);
    cudaGetSymbolAddress((void**)&wap,     g_Wap);
    cudaGetSymbolAddress((void**)&woutp,   g_Woutp);

    static bool attr_set = false;
    if (!attr_set) {
        cudaFuncSetAttribute(fused_gemm_kernel,
                             cudaFuncAttributeMaxDynamicSharedMemorySize, GSMEM_BYTES);
        attr_set = true;
    }

    // fused prepack: A0, A1, all weights
    const unsigned npre = APART + 57344u;
    prepack_all<<<(npre + 255) / 256, 256>>>(
        inputf, query, apackp, qpackp,
        Wv, Woff, Wa, Wout, wvp, woffp, wap, woutp);

    // fused GEMMs 1-3: value / offs / logits  (416 + 416 + 208 = 1040 tiles)
    GemmJob jv  = {apackp, wvp,   bv,   valuep,  256, 2, 416};
    GemmJob jo  = {qpackp, woffp, boff, offsp,   256, 2, 416};
    GemmJob jl  = {qpackp, wap,   ba,   logitsp, 128, 1, 208};
    fused_gemm_kernel<<<GRID_GEMM, 256, GSMEM_BYTES>>>(jv, jo, jl, 3, 1040);

    // softmax + bilinear sampling -> packed acc (writes directly into Apack)
    sample_kernel<<<BATCH * LQ, 256>>>(refp, apackp);

    // out = acc @ W_out + b_out
    GemmJob jout = {apackp, woutp, bout, out, 256, 2, 416};
    fused_gemm_kernel<<<GRID_GEMM, 256, GSMEM_BYTES>>>(jout, jout, jout, 1, 416);
}

// round 15
// speedup vs baseline: 1.2645x; 1.0003x over previous
#include <cuda_runtime.h>
#include <cuda_bf16.h>
#include <math.h>
#include <stdint.h>

#define BATCH 2
#define LQ 13294
#define LEN_IN 13294
#define DM 256
#define NH 8
#define HD 32
#define MROWS (BATCH * LQ)   // 26588
#define MPAD  26624          // 208 * 128
#define QPR   64             // packed uint4 quads per row (16 chunks * 4 tg)
#define GRID_GEMM 304        // 2 CTAs/SM * 152 SMs (GB300)

// ---------------- scratch (device globals; no allocations allowed) ----------
__device__ float g_value[(size_t)BATCH * LEN_IN * DM];   // [B, LEN_IN, NH, HD]
__device__ float g_offs[(size_t)BATCH * LQ * DM];        // [B, LQ, NH, 16, 2]
__device__ float g_logits[(size_t)BATCH * LQ * NH * 16]; // [B, LQ, NH, 16]

__device__ uint4 g_Apack[(size_t)MPAD * QPR];            // inputf pack, reused for acc
__device__ uint4 g_Qpack[(size_t)MPAD * QPR];            // query pack
__device__ uint4 g_Wvp[256 * QPR];
__device__ uint4 g_Woffp[256 * QPR];
__device__ uint4 g_Wap[128 * QPR];
__device__ uint4 g_Woutp[256 * QPR];

// ---------------- helpers ---------------------------------------------------
__device__ __forceinline__ void mma_bf16(float* d,
    unsigned a0, unsigned a1, unsigned a2, unsigned a3,
    unsigned b0, unsigned b1)
{
    asm volatile(
        "mma.sync.aligned.m16n8k16.row.col.f32.bf16.bf16.f32 "
        "{%0,%1,%2,%3}, {%4,%5,%6,%7}, {%8,%9}, {%0,%1,%2,%3};"
        : "+f"(d[0]), "+f"(d[1]), "+f"(d[2]), "+f"(d[3])
        : "r"(a0), "r"(a1), "r"(a2), "r"(a3), "r"(b0), "r"(b1));
}

__device__ __forceinline__ void cpa16(uint32_t dst, const void* src) {
    asm volatile("cp.async.ca.shared.global [%0], [%1], 16;" :: "r"(dst), "l"(src));
}
#define CPA_COMMIT() asm volatile("cp.async.commit_group;")

__device__ __forceinline__ unsigned pack_hi2(float x0, float x1,
                                             float& l0, float& l1) {
    const __nv_bfloat16 h0 = __float2bfloat16_rn(x0);
    const __nv_bfloat16 h1 = __float2bfloat16_rn(x1);
    l0 = x0 - __bfloat162float(h0);
    l1 = x1 - __bfloat162float(h1);
    __nv_bfloat162 p; p.x = h0; p.y = h1;
    return *reinterpret_cast<unsigned*>(&p);
}
__device__ __forceinline__ unsigned pack_lo2(float l0, float l1) {
    __nv_bfloat162 p;
    p.x = __float2bfloat16_rn(l0);
    p.y = __float2bfloat16_rn(l1);
    return *reinterpret_cast<unsigned*>(&p);
}
__device__ __forceinline__ uint4 pack_quad(float x0, float x1, float x2, float x3) {
    float l0, l1, l2, l3;
    uint4 q;
    q.x = pack_hi2(x0, x1, l0, l1);
    q.y = pack_hi2(x2, x3, l2, l3);
    q.z = pack_lo2(l0, l1);
    q.w = pack_lo2(l2, l3);
    return q;
}

// ---------------- fused prepack (A0, A1, all weights in one launch) ----------
#define APART (2u * MPAD * 64u)
__global__ __launch_bounds__(256) void prepack_all(
    const float* __restrict__ A0, const float* __restrict__ A1,
    uint4* __restrict__ P0, uint4* __restrict__ P1,
    const float* __restrict__ Wv,  const float* __restrict__ Woff,
    const float* __restrict__ Wa,  const float* __restrict__ Wout,
    uint4* __restrict__ wvp, uint4* __restrict__ woffp,
    uint4* __restrict__ wap, uint4* __restrict__ woutp)
{
    const unsigned t = blockIdx.x * 256 + threadIdx.x;
    if (t < APART) {
        const unsigned HALF = (unsigned)MPAD * 64;
        const float* A = (t < HALF) ? A0 : A1;
        uint4* P = (t < HALF) ? P0 : P1;
        const unsigned lt = (t < HALF) ? t : t - HALF;
        const unsigned row = lt >> 6;
        const unsigned c = (lt >> 2) & 15, tg = lt & 3;
        float x0 = 0.f, x1 = 0.f, x2 = 0.f, x3 = 0.f;
        if (row < (unsigned)MROWS) {
            const float* a = A + (size_t)row * 256 + c * 16 + 2 * tg;
            x0 = a[0]; x1 = a[1]; x2 = a[8]; x3 = a[9];
        }
        P[lt] = pack_quad(x0, x1, x2, x3);
    } else {
        const unsigned u = t - APART;   // < 57344
        const float* B; uint4* Bp; unsigned N, lt;
        if (u < 16384)      { B = Wv;   Bp = wvp;   N = 256; lt = u; }
        else if (u < 32768) { B = Woff; Bp = woffp; N = 256; lt = u - 16384; }
        else if (u < 40960) { B = Wa;   Bp = wap;   N = 128; lt = u - 32768; }
        else                { B = Wout; Bp = woutp; N = 256; lt = u - 40960; }
        const unsigned col = lt >> 6;
        const unsigned c = (lt >> 2) & 15, tg = lt & 3;
        const unsigned k = c * 16 + 2 * tg;
        const float x0 = B[(k + 0) * N + col];
        const float x1 = B[(k + 1) * N + col];
        const float x2 = B[(k + 8) * N + col];
        const float x3 = B[(k + 9) * N + col];
        Bp[lt] = pack_quad(x0, x1, x2, x3);
    }
}

// ---------------- tensor-core GEMM tile (3xBF16 split, prepacked) -----------
// BM=BN=128, BK=16 (1 k16 step/chunk), 16 chunks, 4-stage cp.async ring.
// 256 threads (8 warps: 2 M x 4 N), warp tile 64x32. Row stride 4 quads
// (64 B, conflict-free: phases split banks 0-15 / 16-31).
#define STAGE_QUADS 1024                      // A 512 + B 512 (16 KB)
#define NSTAGE 4
#define GSMEM_BYTES (NSTAGE * STAGE_QUADS * 16)   // 64 KB

struct GemmJob {
    const uint4* Ap;
    const uint4* Bp;
    const float* bias;
    float* C;
    int N;       // 256 or 128
    int ncols;   // N / 128
    int ntiles;  // ncols * 208
};

__device__ __forceinline__ void gemm_tile(
    const uint4* __restrict__ Ap, const uint4* __restrict__ Bp,
    const float* __restrict__ bias, float* __restrict__ C,
    int N, int bm, int bn, uint4* smem)
{
    const int tid = threadIdx.x;
    const int lane = tid & 31;
    const int wid = tid >> 5;
    const int warp_m = wid & 1;
    const int warp_n = wid >> 1;
    const int g  = lane >> 2;
    const int tg = lane & 3;

    const uint32_t smem_u32 = (uint32_t)__cvta_generic_to_shared(smem);
    const int NCH = 16;

    float acc[4][4][4];
    #pragma unroll
    for (int i = 0; i < 4; ++i)
        #pragma unroll
        for (int j = 0; j < 4; ++j)
            #pragma unroll
            for (int e = 0; e < 4; ++e) acc[i][j][e] = 0.f;

    // chunk c covers quads [c*4, c*4+4) of each row; 512 quads/operand, 2/thread
    auto load_chunk = [&](int buf, int c) {
        const uint32_t abase = smem_u32 + (uint32_t)(buf * STAGE_QUADS) * 16;
        const uint32_t bbase = abase + 512u * 16;
        #pragma unroll
        for (int p = 0; p < 2; ++p) {
            const int idx = tid + p * 256;
            const int row = idx >> 2, qf = idx & 3;
            cpa16(abase + (uint32_t)(row * 4 + qf) * 16,
                  Ap + (size_t)(bm + row) * QPR + c * 4 + qf);
        }
        #pragma unroll
        for (int p = 0; p < 2; ++p) {
            const int idx = tid + p * 256;
            const int col = idx >> 2, qf = idx & 3;
            cpa16(bbase + (uint32_t)(col * 4 + qf) * 16,
                  Bp + (size_t)(bn + col) * QPR + c * 4 + qf);
        }
        CPA_COMMIT();
    };

    load_chunk(0, 0);
    load_chunk(1, 1);
    load_chunk(2, 2);

    for (int c = 0; c < NCH; ++c) {
        if (c <= 13)      asm volatile("cp.async.wait_group 2;");
        else if (c == 14) asm volatile("cp.async.wait_group 1;");
        else              asm volatile("cp.async.wait_group 0;");
        __syncthreads();
        // load(c+3) writes buf (c-1)&3; every warp passed compute(c-1) to
        // reach this barrier, so reuse is safe with ONE barrier per chunk.
        if (c + 3 < NCH) load_chunk((c + 3) & 3, c + 3);

        const uint4* As_ = smem + (c & 3) * STAGE_QUADS;
        const uint4* Bs_ = As_ + 512;

        uint4 bf[4];
        #pragma unroll
        for (int ni = 0; ni < 4; ++ni)
            bf[ni] = Bs_[(warp_n * 32 + ni * 8 + g) * 4 + tg];

        #pragma unroll
        for (int mi = 0; mi < 4; ++mi) {
            const uint4 a0 = As_[(warp_m * 64 + mi * 16 + g) * 4 + tg];
            const uint4 a1 = As_[(warp_m * 64 + mi * 16 + g + 8) * 4 + tg];
            #pragma unroll
            for (int ni = 0; ni < 4; ++ni) {
                mma_bf16(acc[mi][ni], a0.x, a1.x, a0.y, a1.y, bf[ni].x, bf[ni].y);
                mma_bf16(acc[mi][ni], a0.x, a1.x, a0.y, a1.y, bf[ni].z, bf[ni].w);
                mma_bf16(acc[mi][ni], a0.z, a1.z, a0.w, a1.w, bf[ni].x, bf[ni].y);
            }
        }
    }
    __syncthreads();   // all buffers free before next tile's loads

    // epilogue: bias hoisted to registers
    float bxr[4], byr[4];
    #pragma unroll
    for (int ni = 0; ni < 4; ++ni) {
        const int col = bn + warp_n * 32 + ni * 8 + 2 * tg;
        bxr[ni] = bias[col];
        byr[ni] = bias[col + 1];
    }
    #pragma unroll
    for (int mi = 0; mi < 4; ++mi) {
        const int row0 = bm + warp_m * 64 + mi * 16 + g;
        const int row1 = row0 + 8;
        #pragma unroll
        for (int ni = 0; ni < 4; ++ni) {
            const int col = bn + warp_n * 32 + ni * 8 + 2 * tg;
            if (row0 < MROWS) {
                float2 v = {acc[mi][ni][0] + bxr[ni], acc[mi][ni][1] + byr[ni]};
                *reinterpret_cast<float2*>(C + (size_t)row0 * N + col) = v;
            }
            if (row1 < MROWS) {
                float2 v = {acc[mi][ni][2] + bxr[ni], acc[mi][ni][3] + byr[ni]};
                *reinterpret_cast<float2*>(C + (size_t)row1 * N + col) = v;
            }
        }
    }
}

__global__ __launch_bounds__(256, 2) void fused_gemm_kernel(
    GemmJob j0, GemmJob j1, GemmJob j2, int njobs, int total)
{
    extern __shared__ uint4 smem[];
    for (int t = blockIdx.x; t < total; t += gridDim.x) {
        GemmJob jb = j0;
        int lt = t;
        if (njobs > 1 && lt >= jb.ntiles) {
            lt -= jb.ntiles; jb = j1;
            if (njobs > 2 && lt >= jb.ntiles) { lt -= jb.ntiles; jb = j2; }
        }
        int bm, bn;
        if (jb.ncols == 2) { bm = (lt >> 1) * 128; bn = (lt & 1) * 128; }
        else               { bm = lt * 128;        bn = 0; }
        gemm_tile(jb.Ap, jb.Bp, jb.bias, jb.C, jb.N, bm, bn, smem);
    }
}

// ---------------- sampling + softmax + fused bf16 hi/lo packing -------------
// (unchanged from R14 — best measured configuration)
__global__ __launch_bounds__(256) void sample_kernel(
    const float* __restrict__ refp, uint4* __restrict__ AccPack)
{
    __shared__ __align__(16) int2  comb[NH][16][4];
    __shared__ __align__(16) float swacc[NH][32];

    const int bq = blockIdx.x;
    const int b  = (bq >= LQ) ? 1 : 0;
    const int tid = threadIdx.x;
    const int h  = tid >> 5;
    const int lane = tid & 31;

    float logit = -INFINITY;
    if (lane < 16) logit = g_logits[((unsigned)bq * NH + h) * 16 + lane];
    float m = logit;
    #pragma unroll
    for (int o = 16; o > 0; o >>= 1) m = fmaxf(m, __shfl_xor_sync(0xffffffffu, m, o));
    float e = (lane < 16) ? __expf(logit - m) : 0.f;
    float s = e;
    #pragma unroll
    for (int o = 16; o > 0; o >>= 1) s += __shfl_xor_sync(0xffffffffu, s, o);
    const float wt = e / s;

    if (lane < 16) {
        const int LH[4] = {100, 50, 25, 13};
        const int LS[4] = {0, 10000, 12500, 13125};
        const int l = lane >> 2;
        const int w = LH[l], hh = LH[l], s0 = LS[l];
        const float lw = (float)w, lh = (float)hh;

        const float2 off = *reinterpret_cast<const float2*>(
            g_offs + (((unsigned)bq * NH + h) * 16 + lane) * 2);
        const float2 rp = *reinterpret_cast<const float2*>(refp + (unsigned)bq * 8 + l * 2);

        const float x = (rp.x + off.x / lw) * lw - 0.5f;
        const float y = (rp.y + off.y / lh) * lh - 0.5f;
        const float fx = floorf(x), fy = floorf(y);
        const float tx = x - fx, ty = y - fy;
        const int jx = (int)fx, jy = (int)fy;

        const bool xv0 = (jx >= 0) && (jx < w);
        const bool xv1 = (jx + 1 >= 0) && (jx + 1 < w);
        const bool yv0 = (jy >= 0) && (jy < hh);
        const bool yv1 = (jy + 1 >= 0) && (jy + 1 < hh);

        const int cx0 = min(max(jx, 0), w - 1);
        const int cx1 = min(max(jx + 1, 0), w - 1);
        const int cy0 = min(max(jy, 0), hh - 1);
        const int cy1 = min(max(jy + 1, 0), hh - 1);

        const float wx1 = tx, wx0 = 1.f - tx;
        const float wy1 = ty, wy0 = 1.f - ty;

        const float w0 = (xv0 && yv0) ? wt * wx0 * wy0 : 0.f;
        const float w1 = (xv1 && yv0) ? wt * wx1 * wy0 : 0.f;
        const float w2 = (xv0 && yv1) ? wt * wx0 * wy1 : 0.f;
        const float w3 = (xv1 && yv1) ? wt * wx1 * wy1 : 0.f;

        comb[h][lane][0] = make_int2((s0 + cy0 * w + cx0) << 10, __float_as_int(w0));
        comb[h][lane][1] = make_int2((s0 + cy0 * w + cx1) << 10, __float_as_int(w1));
        comb[h][lane][2] = make_int2((s0 + cy1 * w + cx0) << 10, __float_as_int(w2));
        comb[h][lane][3] = make_int2((s0 + cy1 * w + cx1) << 10, __float_as_int(w3));
    }
    __syncwarp();

    const int sub = lane >> 3;
    const int cl  = lane & 7;
    const char* __restrict__ base = (const char*)(
        g_value + ((unsigned)b * LEN_IN) * DM + h * HD + cl * 4);

    float4 acc = {0.f, 0.f, 0.f, 0.f};

    {
        float4 v[8];
        #pragma unroll
        for (int p = 0; p < 8; ++p)
            v[p] = __ldcg(reinterpret_cast<const float4*>(base + comb[h][p][sub].x));
        #pragma unroll
        for (int p = 0; p < 8; ++p) {
            const float w = __int_as_float(comb[h][p][sub].y);
            acc.x += w * v[p].x;
            acc.y += w * v[p].y;
            acc.z += w * v[p].z;
            acc.w += w * v[p].w;
        }
    }
    {
        float4 v[8];
        #pragma unroll
        for (int p = 0; p < 8; ++p)
            v[p] = __ldg(reinterpret_cast<const float4*>(base + comb[h][p + 8][sub].x));
        #pragma unroll
        for (int p = 0; p < 8; ++p) {
            const float w = __int_as_float(comb[h][p + 8][sub].y);
            acc.x += w * v[p].x;
            acc.y += w * v[p].y;
            acc.z += w * v[p].z;
            acc.w += w * v[p].w;
        }
    }

    #pragma unroll
    for (int o = 8; o <= 16; o <<= 1) {
        acc.x += __shfl_xor_sync(0xffffffffu, acc.x, o);
        acc.y += __shfl_xor_sync(0xffffffffu, acc.y, o);
        acc.z += __shfl_xor_sync(0xffffffffu, acc.z, o);
        acc.w += __shfl_xor_sync(0xffffffffu, acc.w, o);
    }
    if (sub == 0)
        *reinterpret_cast<float4*>(&swacc[h][cl * 4]) = acc;
    __syncwarp();

    if (lane < 8) {
        const int cloc = lane >> 2, tg = lane & 3;
        const int bs = cloc * 16 + 2 * tg;
        AccPack[(size_t)bq * QPR + h * 8 + cloc * 4 + tg] =
            pack_quad(swacc[h][bs], swacc[h][bs + 1],
                      swacc[h][bs + 8], swacc[h][bs + 9]);
    }
}

// ---------------- launch ----------------------------------------------------
extern "C" void kernel_launch(void* const* d_in, const int* in_sizes, int n_in,
                              void* d_out, int out_size)
{
    const float* query  = (const float*)d_in[0];
    const float* refp   = (const float*)d_in[1];
    const float* inputf = (const float*)d_in[2];
    const float* Wv   = (const float*)d_in[4];
    const float* bv   = (const float*)d_in[5];
    const float* Woff = (const float*)d_in[6];
    const float* boff = (const float*)d_in[7];
    const float* Wa   = (const float*)d_in[8];
    const float* ba   = (const float*)d_in[9];
    const float* Wout = (const float*)d_in[10];
    const float* bout = (const float*)d_in[11];
    float* out = (float*)d_out;

    float *valuep, *offsp, *logitsp;
    uint4 *apackp, *qpackp, *wvp, *woffp, *wap, *woutp;
    cudaGetSymbolAddress((void**)&valuep,  g_value);
    cudaGetSymbolAddress((void**)&offsp,   g_offs);
    cudaGetSymbolAddress((void**)&logitsp, g_logits);
    cudaGetSymbolAddress((void**)&apackp,  g_Apack);
    cudaGetSymbolAddress((void**)&qpackp,  g_Qpack);
    cudaGetSymbolAddress((void**)&wvp,     g_Wvp);
    cudaGetSymbolAddress((void**)&woffp,   g_Woffp);
    cudaGetSymbolAddress((void**)&wap,     g_Wap);
    cudaGetSymbolAddress((void**)&woutp,   g_Woutp);

    static bool attr_set = false;
    if (!attr_set) {
        cudaFuncSetAttribute(fused_gemm_kernel,
                             cudaFuncAttributeMaxDynamicSharedMemorySize, GSMEM_BYTES);
        attr_set = true;
    }

    // fused prepack: A0, A1, all weights
    const unsigned npre = APART + 57344u;
    prepack_all<<<(npre + 255) / 256, 256>>>(
        inputf, query, apackp, qpackp,
        Wv, Woff, Wa, Wout, wvp, woffp, wap, woutp);

    // fused GEMMs 1-3: value / offs / logits  (416 + 416 + 208 = 1040 tiles)
    GemmJob jv  = {apackp, wvp,   bv,   valuep,  256, 2, 416};
    GemmJob jo  = {qpackp, woffp, boff, offsp,   256, 2, 416};
    GemmJob jl  = {qpackp, wap,   ba,   logitsp, 128, 1, 208};
    fused_gemm_kernel<<<GRID_GEMM, 256, GSMEM_BYTES>>>(jv, jo, jl, 3, 1040);

    // softmax + bilinear sampling -> packed acc (writes directly into Apack)
    sample_kernel<<<BATCH * LQ, 256>>>(refp, apackp);

    // out = acc @ W_out + b_out
    GemmJob jout = {apackp, woutp, bout, out, 256, 2, 416};
    fused_gemm_kernel<<<GRID_GEMM, 256, GSMEM_BYTES>>>(jout, jout, jout, 1, 416);
}

// round 16
// speedup vs baseline: 1.2750x; 1.0083x over previous
#include <cuda_runtime.h>
#include <cuda_bf16.h>
#include <cuda_fp16.h>
#include <math.h>
#include <stdint.h>

#define BATCH 2
#define LQ 13294
#define LEN_IN 13294
#define DM 256
#define NH 8
#define HD 32
#define MROWS (BATCH * LQ)   // 26588
#define MPAD  26624          // 208 * 128
#define QPR   64             // packed uint4 quads per row (16 chunks * 4 tg)
#define GRID_GEMM 304        // 2 CTAs/SM * 152 SMs (GB300)
#define PLANE 13296          // padded tokens per (b,h) plane

// ---------------- scratch (device globals; no allocations allowed) ----------
__device__ __half g_value[(size_t)BATCH * NH * PLANE * HD]; // [b,h,token,32ch] fp16
__device__ float g_offs[(size_t)BATCH * LQ * DM];        // [B, LQ, NH, 16, 2]
__device__ float g_logits[(size_t)BATCH * LQ * NH * 16]; // [B, LQ, NH, 16]

__device__ uint4 g_Apack[(size_t)MPAD * QPR];            // inputf pack, reused for acc
__device__ uint4 g_Qpack[(size_t)MPAD * QPR];            // query pack
__device__ uint4 g_Wvp[256 * QPR];
__device__ uint4 g_Woffp[256 * QPR];
__device__ uint4 g_Wap[128 * QPR];
__device__ uint4 g_Woutp[256 * QPR];

// ---------------- helpers ---------------------------------------------------
__device__ __forceinline__ void mma_bf16(float* d,
    unsigned a0, unsigned a1, unsigned a2, unsigned a3,
    unsigned b0, unsigned b1)
{
    asm volatile(
        "mma.sync.aligned.m16n8k16.row.col.f32.bf16.bf16.f32 "
        "{%0,%1,%2,%3}, {%4,%5,%6,%7}, {%8,%9}, {%0,%1,%2,%3};"
        : "+f"(d[0]), "+f"(d[1]), "+f"(d[2]), "+f"(d[3])
        : "r"(a0), "r"(a1), "r"(a2), "r"(a3), "r"(b0), "r"(b1));
}

__device__ __forceinline__ void cpa16(uint32_t dst, const void* src) {
    asm volatile("cp.async.ca.shared.global [%0], [%1], 16;" :: "r"(dst), "l"(src));
}
#define CPA_COMMIT() asm volatile("cp.async.commit_group;")

__device__ __forceinline__ unsigned pack_hi2(float x0, float x1,
                                             float& l0, float& l1) {
    const __nv_bfloat16 h0 = __float2bfloat16_rn(x0);
    const __nv_bfloat16 h1 = __float2bfloat16_rn(x1);
    l0 = x0 - __bfloat162float(h0);
    l1 = x1 - __bfloat162float(h1);
    __nv_bfloat162 p; p.x = h0; p.y = h1;
    return *reinterpret_cast<unsigned*>(&p);
}
__device__ __forceinline__ unsigned pack_lo2(float l0, float l1) {
    __nv_bfloat162 p;
    p.x = __float2bfloat16_rn(l0);
    p.y = __float2bfloat16_rn(l1);
    return *reinterpret_cast<unsigned*>(&p);
}
__device__ __forceinline__ uint4 pack_quad(float x0, float x1, float x2, float x3) {
    float l0, l1, l2, l3;
    uint4 q;
    q.x = pack_hi2(x0, x1, l0, l1);
    q.y = pack_hi2(x2, x3, l2, l3);
    q.z = pack_lo2(l0, l1);
    q.w = pack_lo2(l2, l3);
    return q;
}

// ---------------- fused prepack (A0, A1, all weights in one launch) ----------
#define APART (2u * MPAD * 64u)
__global__ __launch_bounds__(256) void prepack_all(
    const float* __restrict__ A0, const float* __restrict__ A1,
    uint4* __restrict__ P0, uint4* __restrict__ P1,
    const float* __restrict__ Wv,  const float* __restrict__ Woff,
    const float* __restrict__ Wa,  const float* __restrict__ Wout,
    uint4* __restrict__ wvp, uint4* __restrict__ woffp,
    uint4* __restrict__ wap, uint4* __restrict__ woutp)
{
    const unsigned t = blockIdx.x * 256 + threadIdx.x;
    if (t < APART) {
        const unsigned HALF = (unsigned)MPAD * 64;
        const float* A = (t < HALF) ? A0 : A1;
        uint4* P = (t < HALF) ? P0 : P1;
        const unsigned lt = (t < HALF) ? t : t - HALF;
        const unsigned row = lt >> 6;
        const unsigned c = (lt >> 2) & 15, tg = lt & 3;
        float x0 = 0.f, x1 = 0.f, x2 = 0.f, x3 = 0.f;
        if (row < (unsigned)MROWS) {
            const float* a = A + (size_t)row * 256 + c * 16 + 2 * tg;
            x0 = a[0]; x1 = a[1]; x2 = a[8]; x3 = a[9];
        }
        P[lt] = pack_quad(x0, x1, x2, x3);
    } else {
        const unsigned u = t - APART;   // < 57344
        const float* B; uint4* Bp; unsigned N, lt;
        if (u < 16384)      { B = Wv;   Bp = wvp;   N = 256; lt = u; }
        else if (u < 32768) { B = Woff; Bp = woffp; N = 256; lt = u - 16384; }
        else if (u < 40960) { B = Wa;   Bp = wap;   N = 128; lt = u - 32768; }
        else                { B = Wout; Bp = woutp; N = 256; lt = u - 40960; }
        const unsigned col = lt >> 6;
        const unsigned c = (lt >> 2) & 15, tg = lt & 3;
        const unsigned k = c * 16 + 2 * tg;
        const float x0 = B[(k + 0) * N + col];
        const float x1 = B[(k + 1) * N + col];
        const float x2 = B[(k + 8) * N + col];
        const float x3 = B[(k + 9) * N + col];
        Bp[lt] = pack_quad(x0, x1, x2, x3);
    }
}

// ---------------- tensor-core GEMM tile (3xBF16 split, prepacked) -----------
// BM=BN=128, BK=16 (1 k16 step/chunk), 16 chunks, 4-stage cp.async ring.
#define STAGE_QUADS 1024                      // A 512 + B 512 (16 KB)
#define NSTAGE 4
#define GSMEM_BYTES (NSTAGE * STAGE_QUADS * 16)   // 64 KB

struct GemmJob {
    const uint4* Ap;
    const uint4* Bp;
    const float* bias;
    float* C;
    int N;          // 256 or 128
    int ncols;      // N / 128
    int ntiles;     // ncols * 208
    int trans_half; // 1 -> store fp16 transposed to [b,h,token,ch] planes
};

__device__ __forceinline__ void gemm_tile(
    const uint4* __restrict__ Ap, const uint4* __restrict__ Bp,
    const float* __restrict__ bias, float* __restrict__ C,
    int N, int bm, int bn, int trans_half, uint4* smem)
{
    const int tid = threadIdx.x;
    const int lane = tid & 31;
    const int wid = tid >> 5;
    const int warp_m = wid & 1;
    const int warp_n = wid >> 1;
    const int g  = lane >> 2;
    const int tg = lane & 3;

    const uint32_t smem_u32 = (uint32_t)__cvta_generic_to_shared(smem);
    const int NCH = 16;

    float acc[4][4][4];
    #pragma unroll
    for (int i = 0; i < 4; ++i)
        #pragma unroll
        for (int j = 0; j < 4; ++j)
            #pragma unroll
            for (int e = 0; e < 4; ++e) acc[i][j][e] = 0.f;

    auto load_chunk = [&](int buf, int c) {
        const uint32_t abase = smem_u32 + (uint32_t)(buf * STAGE_QUADS) * 16;
        const uint32_t bbase = abase + 512u * 16;
        #pragma unroll
        for (int p = 0; p < 2; ++p) {
            const int idx = tid + p * 256;
            const int row = idx >> 2, qf = idx & 3;
            cpa16(abase + (uint32_t)(row * 4 + qf) * 16,
                  Ap + (size_t)(bm + row) * QPR + c * 4 + qf);
        }
        #pragma unroll
        for (int p = 0; p < 2; ++p) {
            const int idx = tid + p * 256;
            const int col = idx >> 2, qf = idx & 3;
            cpa16(bbase + (uint32_t)(col * 4 + qf) * 16,
                  Bp + (size_t)(bn + col) * QPR + c * 4 + qf);
        }
        CPA_COMMIT();
    };

    load_chunk(0, 0);
    load_chunk(1, 1);
    load_chunk(2, 2);

    for (int c = 0; c < NCH; ++c) {
        if (c <= 13)      asm volatile("cp.async.wait_group 2;");
        else if (c == 14) asm volatile("cp.async.wait_group 1;");
        else              asm volatile("cp.async.wait_group 0;");
        __syncthreads();
        if (c + 3 < NCH) load_chunk((c + 3) & 3, c + 3);

        const uint4* As_ = smem + (c & 3) * STAGE_QUADS;
        const uint4* Bs_ = As_ + 512;

        uint4 bf[4];
        #pragma unroll
        for (int ni = 0; ni < 4; ++ni)
            bf[ni] = Bs_[(warp_n * 32 + ni * 8 + g) * 4 + tg];

        #pragma unroll
        for (int mi = 0; mi < 4; ++mi) {
            const uint4 a0 = As_[(warp_m * 64 + mi * 16 + g) * 4 + tg];
            const uint4 a1 = As_[(warp_m * 64 + mi * 16 + g + 8) * 4 + tg];
            #pragma unroll
            for (int ni = 0; ni < 4; ++ni) {
                mma_bf16(acc[mi][ni], a0.x, a1.x, a0.y, a1.y, bf[ni].x, bf[ni].y);
                mma_bf16(acc[mi][ni], a0.x, a1.x, a0.y, a1.y, bf[ni].z, bf[ni].w);
                mma_bf16(acc[mi][ni], a0.z, a1.z, a0.w, a1.w, bf[ni].x, bf[ni].y);
            }
        }
    }
    __syncthreads();

    float bxr[4], byr[4];
    #pragma unroll
    for (int ni = 0; ni < 4; ++ni) {
        const int col = bn + warp_n * 32 + ni * 8 + 2 * tg;
        bxr[ni] = bias[col];
        byr[ni] = bias[col + 1];
    }
    #pragma unroll
    for (int mi = 0; mi < 4; ++mi) {
        const int row0 = bm + warp_m * 64 + mi * 16 + g;
        const int row1 = row0 + 8;
        #pragma unroll
        for (int ni = 0; ni < 4; ++ni) {
            const int col = bn + warp_n * 32 + ni * 8 + 2 * tg;
            if (trans_half) {
                __half* V = reinterpret_cast<__half*>(C);
                const int head = col >> 5, chp = col & 31;
                if (row0 < MROWS) {
                    const int bb = (row0 >= LEN_IN) ? 1 : 0;
                    const int tok = row0 - bb * LEN_IN;
                    *reinterpret_cast<__half2*>(
                        V + ((size_t)(bb * NH + head) * PLANE + tok) * HD + chp) =
                        __floats2half2_rn(acc[mi][ni][0] + bxr[ni], acc[mi][ni][1] + byr[ni]);
                }
                if (row1 < MROWS) {
                    const int bb = (row1 >= LEN_IN) ? 1 : 0;
                    const int tok = row1 - bb * LEN_IN;
                    *reinterpret_cast<__half2*>(
                        V + ((size_t)(bb * NH + head) * PLANE + tok) * HD + chp) =
                        __floats2half2_rn(acc[mi][ni][2] + bxr[ni], acc[mi][ni][3] + byr[ni]);
                }
            } else {
                if (row0 < MROWS) {
                    float2 v = {acc[mi][ni][0] + bxr[ni], acc[mi][ni][1] + byr[ni]};
                    *reinterpret_cast<float2*>(C + (size_t)row0 * N + col) = v;
                }
                if (row1 < MROWS) {
                    float2 v = {acc[mi][ni][2] + bxr[ni], acc[mi][ni][3] + byr[ni]};
                    *reinterpret_cast<float2*>(C + (size_t)row1 * N + col) = v;
                }
            }
        }
    }
}

__global__ __launch_bounds__(256, 2) void fused_gemm_kernel(
    GemmJob j0, GemmJob j1, GemmJob j2, int njobs, int total)
{
    extern __shared__ uint4 smem[];
    for (int t = blockIdx.x; t < total; t += gridDim.x) {
        GemmJob jb = j0;
        int lt = t;
        if (njobs > 1 && lt >= jb.ntiles) {
            lt -= jb.ntiles; jb = j1;
            if (njobs > 2 && lt >= jb.ntiles) { lt -= jb.ntiles; jb = j2; }
        }
        int bm, bn;
        if (jb.ncols == 2) { bm = (lt >> 1) * 128; bn = (lt & 1) * 128; }
        else               { bm = lt * 128;        bn = 0; }
        gemm_tile(jb.Ap, jb.Bp, jb.bias, jb.C, jb.N, bm, bn, jb.trans_half, smem);
    }
}

// ---------------- sampling + softmax + fused bf16 hi/lo packing -------------
// One block per (b,q); one warp per head, warps independent. Value is fp16
// head-major [b,h,token,32ch]: token = 64 B, x-adjacent pair = one 128 B line.
// Per point & y-row: pair (t, t+1), t = clamp(jx, 0, w-2), x-weights remapped.
// Lane map: grp = lane>>3 covers {2 points x 2 y-rows}; sl = lane&7 covers the
// 128 B pair (token-half x 16B chunk). One LDG.128 = 4 wavefronts, 8 instrs
// total (32 wf/warp vs 64 in fp32 layout). MLP=8 batched.
__global__ __launch_bounds__(256) void sample_kernel(
    const float* __restrict__ refp, uint4* __restrict__ AccPack)
{
    __shared__ __align__(16) int4  comb[NH][16][2];  // {byte off, wA, wB, pad}
    __shared__ __align__(16) float swacc[NH][32];

    const int bq = blockIdx.x;
    const int b  = (bq >= LQ) ? 1 : 0;
    const int tid = threadIdx.x;
    const int h  = tid >> 5;
    const int lane = tid & 31;

    // ---- softmax over the 16 logits ----
    float logit = -INFINITY;
    if (lane < 16) logit = g_logits[((unsigned)bq * NH + h) * 16 + lane];
    float m = logit;
    #pragma unroll
    for (int o = 16; o > 0; o >>= 1) m = fmaxf(m, __shfl_xor_sync(0xffffffffu, m, o));
    float e = (lane < 16) ? __expf(logit - m) : 0.f;
    float s = e;
    #pragma unroll
    for (int o = 16; o > 0; o >>= 1) s += __shfl_xor_sync(0xffffffffu, s, o);
    const float wt = e / s;

    if (lane < 16) {
        const int LH[4] = {100, 50, 25, 13};
        const int LS[4] = {0, 10000, 12500, 13125};
        const int l = lane >> 2;
        const int w = LH[l], hh = LH[l], s0 = LS[l];
        const float lw = (float)w, lh = (float)hh;

        const float2 off = *reinterpret_cast<const float2*>(
            g_offs + (((unsigned)bq * NH + h) * 16 + lane) * 2);
        const float2 rp = *reinterpret_cast<const float2*>(refp + (unsigned)bq * 8 + l * 2);

        const float x = (rp.x + off.x / lw) * lw - 0.5f;
        const float y = (rp.y + off.y / lh) * lh - 0.5f;
        const float fx = floorf(x), fy = floorf(y);
        const float tx = x - fx, ty = y - fy;
        const int jx = (int)fx, jy = (int)fy;

        const bool xv0 = (jx >= 0) && (jx < w);
        const bool xv1 = (jx + 1 >= 0) && (jx + 1 < w);
        const float u0 = xv0 ? (1.f - tx) : 0.f;
        const float u1 = xv1 ? tx : 0.f;
        const int t = min(max(jx, 0), w - 2);
        const float wA = (t == jx) ? u0 : ((t == jx + 1) ? u1 : 0.f);
        const float wB = ((t + 1) == jx) ? u0 : (((t + 1) == jx + 1) ? u1 : 0.f);

        #pragma unroll
        for (int yc = 0; yc < 2; ++yc) {
            const int iy = jy + yc;
            const bool vy = (iy >= 0) && (iy < hh);
            const int cy = min(max(iy, 0), hh - 1);
            float wy = (yc ? ty : (1.f - ty)) * wt;
            if (!vy) wy = 0.f;
            comb[h][lane][yc] = make_int4(
                (s0 + cy * w + t) * 64,
                __float_as_int(wy * wA),
                __float_as_int(wy * wB), 0);
        }
    }
    __syncwarp();

    // ---- gather: 8 LDG.128, each covering 2 points x 2 y-rows ----
    const int grp = lane >> 3;        // 0..3: {point-slot, y-row}
    const int sl  = lane & 7;
    const int th  = sl >> 2;          // token half (t / t+1)
    const int q   = sl & 3;           // 16 B chunk = 8 channels
    const int psl = grp >> 1;         // point slot within pair
    const int yc  = grp & 1;          // y-row
    const char* __restrict__ base = (const char*)g_value
        + ((size_t)(b * NH + h) * PLANE) * 64 + th * 64 + q * 16;

    float acc[8] = {0.f, 0.f, 0.f, 0.f, 0.f, 0.f, 0.f, 0.f};
    {
        uint4 v[8];
        float wr[8];
        #pragma unroll
        for (int i = 0; i < 8; ++i) {
            const int4 en = comb[h][2 * i + psl][yc];
            wr[i] = __int_as_float(th ? en.z : en.y);
            if (i < 4)   // points 0-7 = levels 0-1: L2-only
                v[i] = __ldcg(reinterpret_cast<const uint4*>(base + en.x));
            else          // levels 2-3: L1-resident
                v[i] = __ldg(reinterpret_cast<const uint4*>(base + en.x));
        }
        #pragma unroll
        for (int i = 0; i < 8; ++i) {
            const __half2* hv = reinterpret_cast<const __half2*>(&v[i]);
            #pragma unroll
            for (int j = 0; j < 4; ++j) {
                const float2 f = __half22float2(hv[j]);
                acc[2 * j]     += wr[i] * f.x;
                acc[2 * j + 1] += wr[i] * f.y;
            }
        }
    }

    // reduce: token-half (xor 4), y-row (xor 8), point-slot (xor 16)
    #pragma unroll
    for (int o = 4; o <= 16; o <<= 1)
        #pragma unroll
        for (int j = 0; j < 8; ++j)
            acc[j] += __shfl_xor_sync(0xffffffffu, acc[j], o);

    if (lane < 4) {   // lane == q: owns channels [q*8, q*8+8)
        *reinterpret_cast<float4*>(&swacc[h][lane * 8]) =
            make_float4(acc[0], acc[1], acc[2], acc[3]);
        *reinterpret_cast<float4*>(&swacc[h][lane * 8 + 4]) =
            make_float4(acc[4], acc[5], acc[6], acc[7]);
    }
    __syncwarp();

    // ---- pack this head's 32 channels into 8 bf16 hi/lo quads ----
    if (lane < 8) {
        const int cloc = lane >> 2, tg = lane & 3;
        const int bs = cloc * 16 + 2 * tg;
        AccPack[(size_t)bq * QPR + h * 8 + cloc * 4 + tg] =
            pack_quad(swacc[h][bs], swacc[h][bs + 1],
                      swacc[h][bs + 8], swacc[h][bs + 9]);
    }
}

// ---------------- launch ----------------------------------------------------
extern "C" void kernel_launch(void* const* d_in, const int* in_sizes, int n_in,
                              void* d_out, int out_size)
{
    const float* query  = (const float*)d_in[0];
    const float* refp   = (const float*)d_in[1];
    const float* inputf = (const float*)d_in[2];
    const float* Wv   = (const float*)d_in[4];
    const float* bv   = (const float*)d_in[5];
    const float* Woff = (const float*)d_in[6];
    const float* boff = (const float*)d_in[7];
    const float* Wa   = (const float*)d_in[8];
    const float* ba   = (const float*)d_in[9];
    const float* Wout = (const float*)d_in[10];
    const float* bout = (const float*)d_in[11];
    float* out = (float*)d_out;

    float *offsp, *logitsp;
    __half* valuep;
    uint4 *apackp, *qpackp, *wvp, *woffp, *wap, *woutp;
    cudaGetSymbolAddress((void**)&valuep,  g_value);
    cudaGetSymbolAddress((void**)&offsp,   g_offs);
    cudaGetSymbolAddress((void**)&logitsp, g_logits);
    cudaGetSymbolAddress((void**)&apackp,  g_Apack);
    cudaGetSymbolAddress((void**)&qpackp,  g_Qpack);
    cudaGetSymbolAddress((void**)&wvp,     g_Wvp);
    cudaGetSymbolAddress((void**)&woffp,   g_Woffp);
    cudaGetSymbolAddress((void**)&wap,     g_Wap);
    cudaGetSymbolAddress((void**)&woutp,   g_Woutp);

    static bool attr_set = false;
    if (!attr_set) {
        cudaFuncSetAttribute(fused_gemm_kernel,
                             cudaFuncAttributeMaxDynamicSharedMemorySize, GSMEM_BYTES);
        attr_set = true;
    }

    // fused prepack: A0, A1, all weights
    const unsigned npre = APART + 57344u;
    prepack_all<<<(npre + 255) / 256, 256>>>(
        inputf, query, apackp, qpackp,
        Wv, Woff, Wa, Wout, wvp, woffp, wap, woutp);

    // fused GEMMs 1-3: value (fp16 transposed out) / offs / logits
    GemmJob jv  = {apackp, wvp,   bv,   (float*)valuep, 256, 2, 416, 1};
    GemmJob jo  = {qpackp, woffp, boff, offsp,          256, 2, 416, 0};
    GemmJob jl  = {qpackp, wap,   ba,   logitsp,        128, 1, 208, 0};
    fused_gemm_kernel<<<GRID_GEMM, 256, GSMEM_BYTES>>>(jv, jo, jl, 3, 1040);

    // softmax + bilinear sampling (fp16 pair gather) -> packed acc
    sample_kernel<<<BATCH * LQ, 256>>>(refp, apackp);

    // out = acc @ W_out + b_out
    GemmJob jout = {apackp, woutp, bout, out, 256, 2, 416, 0};
    fused_gemm_kernel<<<GRID_GEMM, 256, GSMEM_BYTES>>>(jout, jout, jout, 1, 416);
}